// round 15
// baseline (speedup 1.0000x reference)
#include <cuda_runtime.h>
#include <cuda_fp16.h>
#include <cstdint>

#define N_NODES 50000
#define E_EDGES 800000
#define IN_DIM  128
#define H_DIM   96
#define OUT_DIM 64
#define NUM_LAYERS 4
#define NB_SCAN ((N_NODES + 1023) / 1024)
#define HWORDS  48   // 96 channels as half2 words

// ---------------- static device scratch ----------------
__device__ uint32_t g_hh0[(size_t)N_NODES * HWORDS];         // h fp16, buffer 0
__device__ uint32_t g_hh1[(size_t)N_NODES * HWORDS];         // h fp16, buffer 1
__device__ uint32_t g_xh[(size_t)N_NODES * IN_DIM / 2];      // x as half2
__device__ uint32_t g_whalf[(12288 + 3 * 18432) / 2];        // enc_w + conv_W[0..2] fp16
__device__ int      g_counts[N_NODES];
__device__ int      g_offsets[N_NODES + 1];
__device__ int      g_cursor[N_NODES];
__device__ int      g_src_sorted[E_EDGES];
__device__ float2   g_ews[(size_t)E_EDGES * NUM_LAYERS];
__device__ int      g_bsum[NB_SCAN + 1];

// ---------------- helpers ----------------
__device__ __forceinline__ double pack2(float lo, float hi) {
    double d;
    asm("mov.b64 %0, {%1, %2};" : "=d"(d) : "f"(lo), "f"(hi));
    return d;
}
__device__ __forceinline__ void fma2(double& acc, double a, double b) {
    asm("fma.rn.f32x2 %0, %1, %2, %0;" : "+d"(acc) : "d"(a), "d"(b));
}
__device__ __forceinline__ float2 unpack2(double d) {
    float lo, hi;
    asm("mov.b64 {%0, %1}, %2;" : "=f"(lo), "=f"(hi) : "d"(d));
    return make_float2(lo, hi);
}
__device__ __forceinline__ uint32_t smem_u32(const void* p) {
    uint32_t a;
    asm("{ .reg .u64 t; cvta.to.shared.u64 t, %1; cvt.u32.u64 %0, t; }" : "=r"(a) : "l"(p));
    return a;
}
__device__ __forceinline__ void ldmatrix_x4(uint32_t* r, uint32_t addr) {
    asm volatile("ldmatrix.sync.aligned.m8n8.x4.shared.b16 {%0,%1,%2,%3}, [%4];"
                 : "=r"(r[0]), "=r"(r[1]), "=r"(r[2]), "=r"(r[3]) : "r"(addr));
}
__device__ __forceinline__ void ldmatrix_x4_t(uint32_t* r, uint32_t addr) {
    asm volatile("ldmatrix.sync.aligned.m8n8.x4.trans.shared.b16 {%0,%1,%2,%3}, [%4];"
                 : "=r"(r[0]), "=r"(r[1]), "=r"(r[2]), "=r"(r[3]) : "r"(addr));
}
__device__ __forceinline__ void mma16816(float* c, const uint32_t* a, const uint32_t* b) {
    asm volatile("mma.sync.aligned.m16n8k16.row.col.f32.f16.f16.f32 "
                 "{%0,%1,%2,%3},{%4,%5,%6,%7},{%8,%9},{%0,%1,%2,%3};"
                 : "+f"(c[0]), "+f"(c[1]), "+f"(c[2]), "+f"(c[3])
                 : "r"(a[0]), "r"(a[1]), "r"(a[2]), "r"(a[3]), "r"(b[0]), "r"(b[1]));
}

// ---------------- CSR build ----------------
__global__ void hist_kernel(const int* __restrict__ dst) {
    int e = blockIdx.x * blockDim.x + threadIdx.x;
    if (e < E_EDGES) atomicAdd(&g_counts[dst[e]], 1);
}

__global__ void block_scan_kernel() {
    __shared__ int sh[1024];
    int t = threadIdx.x;
    int i = blockIdx.x * 1024 + t;
    int v = (i < N_NODES) ? g_counts[i] : 0;
    sh[t] = v;
    __syncthreads();
    #pragma unroll
    for (int off = 1; off < 1024; off <<= 1) {
        int x = (t >= off) ? sh[t - off] : 0;
        __syncthreads();
        sh[t] += x;
        __syncthreads();
    }
    if (i < N_NODES) g_offsets[i] = sh[t] - v;
    if (t == 1023) g_bsum[blockIdx.x] = sh[1023];
}

__global__ void add_base_kernel() {
    __shared__ int pref[NB_SCAN + 1];
    if (threadIdx.x == 0) {
        int run = 0;
        #pragma unroll
        for (int i = 0; i < NB_SCAN; i++) { pref[i] = run; run += g_bsum[i]; }
        pref[NB_SCAN] = run;
    }
    __syncthreads();
    int i = blockIdx.x * blockDim.x + threadIdx.x;
    if (i < N_NODES) {
        int o = g_offsets[i] + pref[i >> 10];
        g_offsets[i] = o;
        g_cursor[i] = o;
    }
    if (i == N_NODES) g_offsets[N_NODES] = pref[NB_SCAN];
}

__global__ void scatter_kernel(const int* __restrict__ src,
                               const int* __restrict__ dst,
                               const float* __restrict__ conv_ew) {
    int e = blockIdx.x * blockDim.x + threadIdx.x;
    if (e >= E_EDGES) return;
    int d = dst[e];
    int pos = atomicAdd(&g_cursor[d], 1);
    g_src_sorted[pos] = src[e];
    #pragma unroll
    for (int l = 0; l < NUM_LAYERS; l++) {
        float w0 = conv_ew[(size_t)(l * 2 + 0) * E_EDGES + e];
        float w1 = conv_ew[(size_t)(l * 2 + 1) * E_EDGES + e];
        g_ews[(size_t)pos * NUM_LAYERS + l] = make_float2(w0, w1);
    }
}

// ---------------- fp16 prep ----------------
__global__ void wprep_kernel(const float* __restrict__ enc_w,
                             const float* __restrict__ conv_W) {
    int i = blockIdx.x * blockDim.x + threadIdx.x;
    const int total = (12288 + 3 * 18432) / 2;
    if (i >= total) return;
    int off = i * 2;
    float2 v = (off < 12288) ? *(const float2*)(enc_w + off)
                             : *(const float2*)(conv_W + (off - 12288));
    __half2 h = __float22half2_rn(v);
    g_whalf[i] = *(uint32_t*)&h;
}

__global__ void xprep_kernel(const float* __restrict__ x) {
    int i = blockIdx.x * blockDim.x + threadIdx.x;
    const int total = N_NODES * IN_DIM / 2;
    if (i >= total) return;
    float2 v = *(const float2*)(x + i * 2);
    __half2 h = __float22half2_rn(v);
    g_xh[i] = *(uint32_t*)&h;
}

// ---------------- per-node aggregation core (fp32 accumulators) ----------------
__device__ __forceinline__ void agg_core(const uint32_t* __restrict__ hh, int layer,
                                         int beg, int end, int lane, bool lo,
                                         float2& A0, float2& B0, float2& A1, float2& B1) {
    int j = beg;
    for (; j + 7 < end; j += 8) {
        int s[8];
        float2 w[8];
        #pragma unroll
        for (int q = 0; q < 8; q++) {
            s[q] = g_src_sorted[j + q];
            w[q] = g_ews[(size_t)(j + q) * NUM_LAYERS + layer];
        }
        uint32_t ua[8], ub[8];
        #pragma unroll
        for (int q = 0; q < 8; q++) {
            const uint32_t* r = hh + (size_t)s[q] * HWORDS;
            ua[q] = r[lane];
            ub[q] = lo ? r[32 + lane] : 0;
        }
        #pragma unroll
        for (int q = 0; q < 8; q++) {
            float2 x = __half22float2(*(__half2*)&ua[q]);
            A0.x += w[q].x * x.x; A0.y += w[q].x * x.y;
            B0.x += w[q].y * x.x; B0.y += w[q].y * x.y;
            x = __half22float2(*(__half2*)&ub[q]);
            A1.x += w[q].x * x.x; A1.y += w[q].x * x.y;
            B1.x += w[q].y * x.x; B1.y += w[q].y * x.y;
        }
    }
    for (; j + 3 < end; j += 4) {
        int s[4];
        float2 w[4];
        #pragma unroll
        for (int q = 0; q < 4; q++) {
            s[q] = g_src_sorted[j + q];
            w[q] = g_ews[(size_t)(j + q) * NUM_LAYERS + layer];
        }
        uint32_t ua[4], ub[4];
        #pragma unroll
        for (int q = 0; q < 4; q++) {
            const uint32_t* r = hh + (size_t)s[q] * HWORDS;
            ua[q] = r[lane];
            ub[q] = lo ? r[32 + lane] : 0;
        }
        #pragma unroll
        for (int q = 0; q < 4; q++) {
            float2 x = __half22float2(*(__half2*)&ua[q]);
            A0.x += w[q].x * x.x; A0.y += w[q].x * x.y;
            B0.x += w[q].y * x.x; B0.y += w[q].y * x.y;
            x = __half22float2(*(__half2*)&ub[q]);
            A1.x += w[q].x * x.x; A1.y += w[q].x * x.y;
            B1.x += w[q].y * x.x; B1.y += w[q].y * x.y;
        }
    }
    for (; j < end; j++) {
        int s = g_src_sorted[j];
        float2 w = g_ews[(size_t)j * NUM_LAYERS + layer];
        const uint32_t* r = hh + (size_t)s * HWORDS;
        uint32_t u0 = r[lane];
        uint32_t u1 = lo ? r[32 + lane] : 0;
        float2 x = __half22float2(*(__half2*)&u0);
        A0.x += w.x * x.x; A0.y += w.x * x.y; B0.x += w.y * x.x; B0.y += w.y * x.y;
        x = __half22float2(*(__half2*)&u1);
        A1.x += w.x * x.x; A1.y += w.x * x.y; B1.x += w.y * x.x; B1.y += w.y * x.y;
    }
}

// ---------------- fused conv layer 0..2: aggregate (into SMEM) + HMMA GEMM ----------------
__global__ void __launch_bounds__(256)
fused_layer(const uint32_t* __restrict__ hh_in, int layer,
            const __half* __restrict__ Wh, uint32_t* __restrict__ hh_out, int M) {
    constexpr int K = 192, KPAD = 200, NPAD = 104;
    extern __shared__ __half sm[];
    __half* As = sm;                 // [64][200]
    __half* Bs = sm + 64 * KPAD;     // [192][104]
    int tid = threadIdx.x, lane = tid & 31, wid = tid >> 5;
    int blockRow = blockIdx.x * 64;
    bool lo = lane < 16;

    for (int i = tid; i < K * 12; i += 256) {
        int row = i / 12, c = i % 12;
        ((uint4*)(Bs + row * NPAD))[c] = ((const uint4*)(Wh + (size_t)row * 96))[c];
    }

    #pragma unroll 1
    for (int t = 0; t < 8; t++) {
        int row = wid * 8 + t;
        int node = blockRow + row;
        if (node < M) {
            int beg = g_offsets[node];
            int end = g_offsets[node + 1];
            float2 A0 = {0.f, 0.f}, B0 = {0.f, 0.f}, A1 = {0.f, 0.f}, B1 = {0.f, 0.f};
            agg_core(hh_in, layer, beg, end, lane, lo, A0, B0, A1, B1);
            uint32_t* orow = (uint32_t*)(As + row * KPAD);
            __half2 hv;
            hv = __float22half2_rn(A0); orow[lane]      = *(uint32_t*)&hv;
            hv = __float22half2_rn(B0); orow[48 + lane] = *(uint32_t*)&hv;
            if (lo) {
                hv = __float22half2_rn(A1); orow[32 + lane] = *(uint32_t*)&hv;
                hv = __float22half2_rn(B1); orow[80 + lane] = *(uint32_t*)&hv;
            }
        }
    }
    __syncthreads();

    int m0w = (wid & 3) * 16;
    int n0w = (wid >> 2) * 48;
    float acc[6][4];
    #pragma unroll
    for (int nj = 0; nj < 6; nj++)
        #pragma unroll
        for (int q = 0; q < 4; q++) acc[nj][q] = 0.f;

    uint32_t aBase = smem_u32(As), bBase = smem_u32(Bs);
    #pragma unroll
    for (int ks = 0; ks < K / 16; ks++) {
        int k0 = ks * 16;
        uint32_t a[4];
        {
            uint32_t addr = aBase +
                (((m0w + (lane & 7) + (lane & 8)) * KPAD + k0 + ((lane >> 4) << 3)) << 1);
            ldmatrix_x4(a, addr);
        }
        uint32_t b[6][2];
        #pragma unroll
        for (int bj = 0; bj < 3; bj++) {
            uint32_t r[4];
            uint32_t addr = bBase +
                (((k0 + (lane & 15)) * NPAD + n0w + bj * 16 + ((lane >> 4) << 3)) << 1);
            ldmatrix_x4_t(r, addr);
            b[2 * bj][0] = r[0]; b[2 * bj][1] = r[1];
            b[2 * bj + 1][0] = r[2]; b[2 * bj + 1][1] = r[3];
        }
        #pragma unroll
        for (int nj = 0; nj < 6; nj++)
            mma16816(acc[nj], a, b[nj]);
    }

    #pragma unroll
    for (int nj = 0; nj < 6; nj++) {
        int col = n0w + nj * 8 + 2 * (lane & 3);
        int r = blockRow + m0w + (lane >> 2);
        float v0 = fmaxf(acc[nj][0], 0.f);
        float v1 = fmaxf(acc[nj][1], 0.f);
        float v2 = fmaxf(acc[nj][2], 0.f);
        float v3 = fmaxf(acc[nj][3], 0.f);
        if (r < M) {
            __half2 h = __float22half2_rn(make_float2(v0, v1));
            hh_out[(size_t)r * HWORDS + (col >> 1)] = *(uint32_t*)&h;
        }
        if (r + 8 < M) {
            __half2 h = __float22half2_rn(make_float2(v2, v3));
            hh_out[(size_t)(r + 8) * HWORDS + (col >> 1)] = *(uint32_t*)&h;
        }
    }
}

// ---------------- HMMA GEMM (encoder) ----------------
template <int K, bool BIAS>
__global__ void __launch_bounds__(128)
mma_gemm(const __half* __restrict__ Ag, const __half* __restrict__ Wh,
         const float* __restrict__ bias, uint32_t* __restrict__ hh, int M) {
    constexpr int KPAD = (K == 192) ? 200 : 136;
    constexpr int NPAD = 104;
    extern __shared__ __half sm[];
    __half* As = sm;
    __half* Bs = sm + 64 * KPAD;
    int tid = threadIdx.x, lane = tid & 31, wid = tid >> 5;
    int blockRow = blockIdx.x * 64;

    constexpr int ACH = K / 8;
    for (int i = tid; i < 64 * ACH; i += 128) {
        int row = i / ACH, c = i % ACH;
        int gRow = blockRow + row;
        uint4 v = make_uint4(0, 0, 0, 0);
        if (gRow < M) v = ((const uint4*)(Ag + (size_t)gRow * K))[c];
        ((uint4*)(As + row * KPAD))[c] = v;
    }
    for (int i = tid; i < K * 12; i += 128) {
        int row = i / 12, c = i % 12;
        ((uint4*)(Bs + row * NPAD))[c] = ((const uint4*)(Wh + (size_t)row * 96))[c];
    }
    __syncthreads();

    int m0w = (wid & 1) * 32;
    int n0w = (wid >> 1) * 48;
    float acc[2][6][4];
    #pragma unroll
    for (int mi = 0; mi < 2; mi++)
        #pragma unroll
        for (int nj = 0; nj < 6; nj++)
            #pragma unroll
            for (int q = 0; q < 4; q++) acc[mi][nj][q] = 0.f;

    uint32_t aBase = smem_u32(As), bBase = smem_u32(Bs);
    #pragma unroll
    for (int ks = 0; ks < K / 16; ks++) {
        int k0 = ks * 16;
        uint32_t a[2][4];
        #pragma unroll
        for (int mi = 0; mi < 2; mi++) {
            uint32_t addr = aBase +
                (((m0w + mi * 16 + (lane & 7) + (lane & 8)) * KPAD + k0 + ((lane >> 4) << 3)) << 1);
            ldmatrix_x4(a[mi], addr);
        }
        uint32_t b[6][2];
        #pragma unroll
        for (int bj = 0; bj < 3; bj++) {
            uint32_t r[4];
            uint32_t addr = bBase +
                (((k0 + (lane & 15)) * NPAD + n0w + bj * 16 + ((lane >> 4) << 3)) << 1);
            ldmatrix_x4_t(r, addr);
            b[2 * bj][0] = r[0]; b[2 * bj][1] = r[1];
            b[2 * bj + 1][0] = r[2]; b[2 * bj + 1][1] = r[3];
        }
        #pragma unroll
        for (int mi = 0; mi < 2; mi++)
            #pragma unroll
            for (int nj = 0; nj < 6; nj++)
                mma16816(acc[mi][nj], a[mi], b[nj]);
    }

    #pragma unroll
    for (int mi = 0; mi < 2; mi++) {
        #pragma unroll
        for (int nj = 0; nj < 6; nj++) {
            int col = n0w + nj * 8 + 2 * (lane & 3);
            float bx = 0.f, by = 0.f;
            if (BIAS) { float2 bb = *(const float2*)(bias + col); bx = bb.x; by = bb.y; }
            int r = blockRow + m0w + mi * 16 + (lane >> 2);
            float v0 = fmaxf(acc[mi][nj][0] + bx, 0.f);
            float v1 = fmaxf(acc[mi][nj][1] + by, 0.f);
            float v2 = fmaxf(acc[mi][nj][2] + bx, 0.f);
            float v3 = fmaxf(acc[mi][nj][3] + by, 0.f);
            if (r < M) {
                __half2 h = __float22half2_rn(make_float2(v0, v1));
                hh[(size_t)r * HWORDS + (col >> 1)] = *(uint32_t*)&h;
            }
            if (r + 8 < M) {
                __half2 h = __float22half2_rn(make_float2(v2, v3));
                hh[(size_t)(r + 8) * HWORDS + (col >> 1)] = *(uint32_t*)&h;
            }
        }
    }
}

// ---------------- fused layer 3 + decoder (all fp32 tail in one kernel) ----------------
// Phase 1: aggregate fp32 into transposed SMEM At[192][66]
// Phase 2: C1 = relu(At^T @ W3)   (FFMA2, W3 streamed) -> out tail + C1t[96][70]
// Phase 3: out = C1 @ dec_w + dec_b (FFMA2, dec_w streamed)
__global__ void __launch_bounds__(256)
fused_layer3(const uint32_t* __restrict__ hh_in,
             const float* __restrict__ W3, const float* __restrict__ dec_w,
             const float* __restrict__ dec_b, float* __restrict__ out,
             float* __restrict__ outTail, int M) {
    constexpr int ATS = 66;   // At row stride (floats, even for 8B-aligned pairs)
    constexpr int C1S = 70;   // C1t row stride
    extern __shared__ float smf[];
    float* At  = smf;                          // [192][66]
    float* C1t = smf + 192 * ATS;              // [96][70]
    float* Bs  = smf + 192 * ATS + 96 * C1S;   // [16][96] stream buffer (reused)
    int tid = threadIdx.x, lane = tid & 31, wid = tid >> 5;
    int tx = tid & 15, ty = tid >> 4;          // ty 0..15
    int blockRow = blockIdx.x * 64;
    bool lo = lane < 16;

    // ---- Phase 1: aggregation (warp per node, 8 nodes/warp), write transposed ----
    #pragma unroll 1
    for (int t = 0; t < 8; t++) {
        int row = wid * 8 + t;
        int node = blockRow + row;
        float2 A0 = {0.f, 0.f}, B0 = {0.f, 0.f}, A1 = {0.f, 0.f}, B1 = {0.f, 0.f};
        if (node < M) {
            int beg = g_offsets[node];
            int end = g_offsets[node + 1];
            agg_core(hh_in, NUM_LAYERS - 1, beg, end, lane, lo, A0, B0, A1, B1);
        }
        At[(2 * lane) * ATS + row]      = A0.x;
        At[(2 * lane + 1) * ATS + row]  = A0.y;
        At[(96 + 2 * lane) * ATS + row] = B0.x;
        At[(97 + 2 * lane) * ATS + row] = B0.y;
        if (lo) {
            At[(64 + 2 * lane) * ATS + row]  = A1.x;
            At[(65 + 2 * lane) * ATS + row]  = A1.y;
            At[(160 + 2 * lane) * ATS + row] = B1.x;
            At[(161 + 2 * lane) * ATS + row] = B1.y;
        }
    }
    __syncthreads();

    // ---- Phase 2: GEMM1 C1 = relu(agg @ W3), per-thread 4(M) x 6(N) ----
    double acc[2][6];
    #pragma unroll
    for (int i = 0; i < 2; i++)
        #pragma unroll
        for (int j = 0; j < 6; j++) acc[i][j] = 0.0;

    for (int k0 = 0; k0 < 192; k0 += 16) {
        #pragma unroll
        for (int e = tid; e < 16 * 96 / 4; e += 256)
            ((float4*)Bs)[e] = ((const float4*)(W3 + (size_t)k0 * 96))[e];
        __syncthreads();
        #pragma unroll
        for (int kk = 0; kk < 16; kk++) {
            const float* arow = At + (k0 + kk) * ATS + ty * 4;
            double a0 = *(const double*)arow;
            double a1 = *(const double*)(arow + 2);
            double b2[6];
            #pragma unroll
            for (int j = 0; j < 3; j++) {
                float2 t2 = *(const float2*)&Bs[kk * 96 + tx * 6 + 2 * j];
                b2[2 * j + 0] = pack2(t2.x, t2.x);
                b2[2 * j + 1] = pack2(t2.y, t2.y);
            }
            #pragma unroll
            for (int j = 0; j < 6; j++) { fma2(acc[0][j], a0, b2[j]); fma2(acc[1][j], a1, b2[j]); }
        }
        __syncthreads();
    }

    // epilogue1: relu; write out tail + transposed C1t
    #pragma unroll
    for (int i = 0; i < 2; i++) {
        float2 col[6];
        #pragma unroll
        for (int j = 0; j < 6; j++) col[j] = unpack2(acc[i][j]);
        #pragma unroll
        for (int half = 0; half < 2; half++) {
            int r = ty * 4 + 2 * i + half;
            int node = blockRow + r;
            float v[6];
            #pragma unroll
            for (int j = 0; j < 6; j++)
                v[j] = fmaxf(half ? col[j].y : col[j].x, 0.f);
            if (node < M) {
                float* trow = outTail + (size_t)node * H_DIM + tx * 6;
                #pragma unroll
                for (int j = 0; j < 3; j++)
                    *(float2*)(trow + 2 * j) = make_float2(v[2 * j], v[2 * j + 1]);
            }
            #pragma unroll
            for (int j = 0; j < 6; j++)
                C1t[(tx * 6 + j) * C1S + r] = v[j];
        }
    }
    __syncthreads();

    // ---- Phase 3: GEMM2 out = C1 @ dec_w + dec_b, per-thread 4(M) x 4(N) ----
    double acc2[2][4];
    #pragma unroll
    for (int i = 0; i < 2; i++)
        #pragma unroll
        for (int j = 0; j < 4; j++) acc2[i][j] = 0.0;

    for (int k0 = 0; k0 < 96; k0 += 16) {
        #pragma unroll
        for (int e = tid; e < 16 * 64 / 4; e += 256)
            ((float4*)Bs)[e] = ((const float4*)(dec_w + (size_t)k0 * 64))[e];
        __syncthreads();
        #pragma unroll
        for (int kk = 0; kk < 16; kk++) {
            const float* crow = C1t + (k0 + kk) * C1S + ty * 4;
            double a0 = *(const double*)crow;
            double a1 = *(const double*)(crow + 2);
            double b2[4];
            #pragma unroll
            for (int j = 0; j < 2; j++) {
                float2 t2 = *(const float2*)&Bs[kk * 64 + tx * 4 + 2 * j];
                b2[2 * j + 0] = pack2(t2.x, t2.x);
                b2[2 * j + 1] = pack2(t2.y, t2.y);
            }
            #pragma unroll
            for (int j = 0; j < 4; j++) { fma2(acc2[0][j], a0, b2[j]); fma2(acc2[1][j], a1, b2[j]); }
        }
        __syncthreads();
    }

    #pragma unroll
    for (int i = 0; i < 2; i++) {
        float2 col[4];
        #pragma unroll
        for (int j = 0; j < 4; j++) col[j] = unpack2(acc2[i][j]);
        #pragma unroll
        for (int half = 0; half < 2; half++) {
            int node = blockRow + ty * 4 + 2 * i + half;
            if (node >= M) continue;
            float* orow = out + (size_t)node * OUT_DIM + tx * 4;
            #pragma unroll
            for (int j = 0; j < 2; j++) {
                float v0 = (half ? col[2 * j + 0].y : col[2 * j + 0].x) + dec_b[tx * 4 + 2 * j + 0];
                float v1 = (half ? col[2 * j + 1].y : col[2 * j + 1].x) + dec_b[tx * 4 + 2 * j + 1];
                *(float2*)(orow + 2 * j) = make_float2(v0, v1);
            }
        }
    }
}

// ---------------- launch (single stream) ----------------
extern "C" void kernel_launch(void* const* d_in, const int* in_sizes, int n_in,
                              void* d_out, int out_size) {
    const float* x       = (const float*)d_in[0];
    const int*   eidx    = (const int*)d_in[1];
    const float* enc_w   = (const float*)d_in[2];
    const float* enc_b   = (const float*)d_in[3];
    const float* dec_w   = (const float*)d_in[4];
    const float* dec_b   = (const float*)d_in[5];
    const float* conv_W  = (const float*)d_in[6];
    const float* conv_ew = (const float*)d_in[7];
    float* out = (float*)d_out;

    const int* src = eidx;
    const int* dst = eidx + E_EDGES;

    void *p_hh0, *p_hh1, *p_counts, *p_wh, *p_xh;
    cudaGetSymbolAddress(&p_hh0, g_hh0);
    cudaGetSymbolAddress(&p_hh1, g_hh1);
    cudaGetSymbolAddress(&p_counts, g_counts);
    cudaGetSymbolAddress(&p_wh, g_whalf);
    cudaGetSymbolAddress(&p_xh, g_xh);
    uint32_t* hh0 = (uint32_t*)p_hh0;
    uint32_t* hh1 = (uint32_t*)p_hh1;
    const __half* wh = (const __half*)p_wh;
    const __half* xh = (const __half*)p_xh;

    constexpr int SMEM_FUSED = (64 * 200 + 192 * 104) * 2;             // 65536
    constexpr int SMEM_ENC   = (64 * 136 + 128 * 104) * 2;             // 44032
    constexpr int SMEM_L3    = (192 * 66 + 96 * 70 + 16 * 96) * 4;     // 83712
    cudaFuncSetAttribute(fused_layer, cudaFuncAttributeMaxDynamicSharedMemorySize, SMEM_FUSED);
    cudaFuncSetAttribute(mma_gemm<128, true>, cudaFuncAttributeMaxDynamicSharedMemorySize, SMEM_ENC);
    cudaFuncSetAttribute(fused_layer3, cudaFuncAttributeMaxDynamicSharedMemorySize, SMEM_L3);

    // CSR build + fp16 prep
    cudaMemsetAsync(p_counts, 0, N_NODES * sizeof(int));
    hist_kernel<<<(E_EDGES + 255) / 256, 256>>>(dst);
    block_scan_kernel<<<NB_SCAN, 1024>>>();
    add_base_kernel<<<(N_NODES + 256) / 256, 256>>>();
    scatter_kernel<<<(E_EDGES + 255) / 256, 256>>>(src, dst, conv_ew);
    wprep_kernel<<<((12288 + 3 * 18432) / 2 + 255) / 256, 256>>>(enc_w, conv_W);
    xprep_kernel<<<(N_NODES * IN_DIM / 2 + 255) / 256, 256>>>(x);

    int gemmGrid = (N_NODES + 63) / 64;

    // encoder (HMMA): hh0 = relu(x @ enc_w + enc_b)
    mma_gemm<128, true><<<gemmGrid, 128, SMEM_ENC>>>(xh, wh, enc_b, hh0, N_NODES);

    // layers 0..2: fused aggregate+GEMM, double-buffered
    uint32_t* cur = hh0;
    uint32_t* nxt = hh1;
    for (int l = 0; l < NUM_LAYERS - 1; l++) {
        fused_layer<<<gemmGrid, 256, SMEM_FUSED>>>(cur, l, wh + 12288 + l * 18432, nxt, N_NODES);
        uint32_t* t = cur; cur = nxt; nxt = t;
    }

    // layer 3 + decoder, fully fused fp32 tail
    fused_layer3<<<gemmGrid, 256, SMEM_L3>>>(
        cur, conv_W + (size_t)(NUM_LAYERS - 1) * 2 * H_DIM * H_DIM,
        dec_w, dec_b, out, out + (size_t)N_NODES * OUT_DIM, N_NODES);
    (void)in_sizes; (void)n_in; (void)out_size;
}

// round 16
// speedup vs baseline: 1.1868x; 1.1868x over previous
#include <cuda_runtime.h>
#include <cuda_fp16.h>
#include <cstdint>

#define N_NODES 50000
#define E_EDGES 800000
#define IN_DIM  128
#define H_DIM   96
#define OUT_DIM 64
#define NUM_LAYERS 4
#define NB_SCAN ((N_NODES + 1023) / 1024)
#define HWORDS  48   // 96 channels as half2 words

// weight image offsets (halves)
#define WOFF_CONV 12288
#define WOFF_DEC  (12288 + 4 * 18432)
#define WTOTAL    (12288 + 4 * 18432 + 6144)

// ---------------- static device scratch ----------------
__device__ uint32_t g_hh0[(size_t)N_NODES * HWORDS];         // h fp16, buffer 0
__device__ uint32_t g_hh1[(size_t)N_NODES * HWORDS];         // h fp16, buffer 1
__device__ uint32_t g_xh[(size_t)N_NODES * IN_DIM / 2];      // x as half2
__device__ uint32_t g_whalf[WTOTAL / 2];                     // enc_w + conv_W[0..3] + dec_w fp16
__device__ int      g_counts[N_NODES];
__device__ int      g_offsets[N_NODES + 1];
__device__ int      g_cursor[N_NODES];
__device__ int      g_src_sorted[E_EDGES];
__device__ float2   g_ews[(size_t)E_EDGES * NUM_LAYERS];
__device__ int      g_bsum[NB_SCAN + 1];

// ---------------- helpers ----------------
__device__ __forceinline__ uint32_t smem_u32(const void* p) {
    uint32_t a;
    asm("{ .reg .u64 t; cvta.to.shared.u64 t, %1; cvt.u32.u64 %0, t; }" : "=r"(a) : "l"(p));
    return a;
}
__device__ __forceinline__ void ldmatrix_x4(uint32_t* r, uint32_t addr) {
    asm volatile("ldmatrix.sync.aligned.m8n8.x4.shared.b16 {%0,%1,%2,%3}, [%4];"
                 : "=r"(r[0]), "=r"(r[1]), "=r"(r[2]), "=r"(r[3]) : "r"(addr));
}
__device__ __forceinline__ void ldmatrix_x4_t(uint32_t* r, uint32_t addr) {
    asm volatile("ldmatrix.sync.aligned.m8n8.x4.trans.shared.b16 {%0,%1,%2,%3}, [%4];"
                 : "=r"(r[0]), "=r"(r[1]), "=r"(r[2]), "=r"(r[3]) : "r"(addr));
}
__device__ __forceinline__ void mma16816(float* c, const uint32_t* a, const uint32_t* b) {
    asm volatile("mma.sync.aligned.m16n8k16.row.col.f32.f16.f16.f32 "
                 "{%0,%1,%2,%3},{%4,%5,%6,%7},{%8,%9},{%0,%1,%2,%3};"
                 : "+f"(c[0]), "+f"(c[1]), "+f"(c[2]), "+f"(c[3])
                 : "r"(a[0]), "r"(a[1]), "r"(a[2]), "r"(a[3]), "r"(b[0]), "r"(b[1]));
}

// ---------------- CSR build ----------------
__global__ void hist_kernel(const int* __restrict__ dst) {
    int e = blockIdx.x * blockDim.x + threadIdx.x;
    if (e < E_EDGES) atomicAdd(&g_counts[dst[e]], 1);
}

__global__ void block_scan_kernel() {
    __shared__ int sh[1024];
    int t = threadIdx.x;
    int i = blockIdx.x * 1024 + t;
    int v = (i < N_NODES) ? g_counts[i] : 0;
    sh[t] = v;
    __syncthreads();
    #pragma unroll
    for (int off = 1; off < 1024; off <<= 1) {
        int x = (t >= off) ? sh[t - off] : 0;
        __syncthreads();
        sh[t] += x;
        __syncthreads();
    }
    if (i < N_NODES) g_offsets[i] = sh[t] - v;
    if (t == 1023) g_bsum[blockIdx.x] = sh[1023];
}

__global__ void add_base_kernel() {
    __shared__ int pref[NB_SCAN + 1];
    if (threadIdx.x == 0) {
        int run = 0;
        #pragma unroll
        for (int i = 0; i < NB_SCAN; i++) { pref[i] = run; run += g_bsum[i]; }
        pref[NB_SCAN] = run;
    }
    __syncthreads();
    int i = blockIdx.x * blockDim.x + threadIdx.x;
    if (i < N_NODES) {
        int o = g_offsets[i] + pref[i >> 10];
        g_offsets[i] = o;
        g_cursor[i] = o;
    }
    if (i == N_NODES) g_offsets[N_NODES] = pref[NB_SCAN];
}

__global__ void scatter_kernel(const int* __restrict__ src,
                               const int* __restrict__ dst,
                               const float* __restrict__ conv_ew) {
    int e = blockIdx.x * blockDim.x + threadIdx.x;
    if (e >= E_EDGES) return;
    int d = dst[e];
    int pos = atomicAdd(&g_cursor[d], 1);
    g_src_sorted[pos] = src[e];
    #pragma unroll
    for (int l = 0; l < NUM_LAYERS; l++) {
        float w0 = conv_ew[(size_t)(l * 2 + 0) * E_EDGES + e];
        float w1 = conv_ew[(size_t)(l * 2 + 1) * E_EDGES + e];
        g_ews[(size_t)pos * NUM_LAYERS + l] = make_float2(w0, w1);
    }
}

// ---------------- fp16 prep ----------------
__global__ void wprep_kernel(const float* __restrict__ enc_w,
                             const float* __restrict__ conv_W,
                             const float* __restrict__ dec_w) {
    int i = blockIdx.x * blockDim.x + threadIdx.x;
    const int total = WTOTAL / 2;
    if (i >= total) return;
    int off = i * 2;
    float2 v;
    if (off < WOFF_CONV)     v = *(const float2*)(enc_w + off);
    else if (off < WOFF_DEC) v = *(const float2*)(conv_W + (off - WOFF_CONV));
    else                     v = *(const float2*)(dec_w + (off - WOFF_DEC));
    __half2 h = __float22half2_rn(v);
    g_whalf[i] = *(uint32_t*)&h;
}

__global__ void xprep_kernel(const float* __restrict__ x) {
    int i = blockIdx.x * blockDim.x + threadIdx.x;
    const int total = N_NODES * IN_DIM / 2;
    if (i >= total) return;
    float2 v = *(const float2*)(x + i * 2);
    __half2 h = __float22half2_rn(v);
    g_xh[i] = *(uint32_t*)&h;
}

// ---------------- per-node aggregation core (fp32 accumulators) ----------------
__device__ __forceinline__ void agg_core(const uint32_t* __restrict__ hh, int layer,
                                         int beg, int end, int lane, bool lo,
                                         float2& A0, float2& B0, float2& A1, float2& B1) {
    int j = beg;
    for (; j + 7 < end; j += 8) {
        int s[8];
        float2 w[8];
        #pragma unroll
        for (int q = 0; q < 8; q++) {
            s[q] = g_src_sorted[j + q];
            w[q] = g_ews[(size_t)(j + q) * NUM_LAYERS + layer];
        }
        uint32_t ua[8], ub[8];
        #pragma unroll
        for (int q = 0; q < 8; q++) {
            const uint32_t* r = hh + (size_t)s[q] * HWORDS;
            ua[q] = r[lane];
            ub[q] = lo ? r[32 + lane] : 0;
        }
        #pragma unroll
        for (int q = 0; q < 8; q++) {
            float2 x = __half22float2(*(__half2*)&ua[q]);
            A0.x += w[q].x * x.x; A0.y += w[q].x * x.y;
            B0.x += w[q].y * x.x; B0.y += w[q].y * x.y;
            x = __half22float2(*(__half2*)&ub[q]);
            A1.x += w[q].x * x.x; A1.y += w[q].x * x.y;
            B1.x += w[q].y * x.x; B1.y += w[q].y * x.y;
        }
    }
    for (; j + 3 < end; j += 4) {
        int s[4];
        float2 w[4];
        #pragma unroll
        for (int q = 0; q < 4; q++) {
            s[q] = g_src_sorted[j + q];
            w[q] = g_ews[(size_t)(j + q) * NUM_LAYERS + layer];
        }
        uint32_t ua[4], ub[4];
        #pragma unroll
        for (int q = 0; q < 4; q++) {
            const uint32_t* r = hh + (size_t)s[q] * HWORDS;
            ua[q] = r[lane];
            ub[q] = lo ? r[32 + lane] : 0;
        }
        #pragma unroll
        for (int q = 0; q < 4; q++) {
            float2 x = __half22float2(*(__half2*)&ua[q]);
            A0.x += w[q].x * x.x; A0.y += w[q].x * x.y;
            B0.x += w[q].y * x.x; B0.y += w[q].y * x.y;
            x = __half22float2(*(__half2*)&ub[q]);
            A1.x += w[q].x * x.x; A1.y += w[q].x * x.y;
            B1.x += w[q].y * x.x; B1.y += w[q].y * x.y;
        }
    }
    for (; j < end; j++) {
        int s = g_src_sorted[j];
        float2 w = g_ews[(size_t)j * NUM_LAYERS + layer];
        const uint32_t* r = hh + (size_t)s * HWORDS;
        uint32_t u0 = r[lane];
        uint32_t u1 = lo ? r[32 + lane] : 0;
        float2 x = __half22float2(*(__half2*)&u0);
        A0.x += w.x * x.x; A0.y += w.x * x.y; B0.x += w.y * x.x; B0.y += w.y * x.y;
        x = __half22float2(*(__half2*)&u1);
        A1.x += w.x * x.x; A1.y += w.x * x.y; B1.x += w.y * x.x; B1.y += w.y * x.y;
    }
}

// ---------------- fused conv layer: aggregate (into SMEM) + HMMA GEMM ----------------
// TAIL: also write fp32 accumulator results (relu'd, pre-fp16-rounding) to outTail.
template <bool TAIL>
__global__ void __launch_bounds__(256)
fused_layer(const uint32_t* __restrict__ hh_in, int layer,
            const __half* __restrict__ Wh, uint32_t* __restrict__ hh_out,
            float* __restrict__ outTail, int M) {
    constexpr int K = 192, KPAD = 200, NPAD = 104;
    extern __shared__ __half sm[];
    __half* As = sm;                 // [64][200]
    __half* Bs = sm + 64 * KPAD;     // [192][104]
    int tid = threadIdx.x, lane = tid & 31, wid = tid >> 5;
    int blockRow = blockIdx.x * 64;
    bool lo = lane < 16;

    for (int i = tid; i < K * 12; i += 256) {
        int row = i / 12, c = i % 12;
        ((uint4*)(Bs + row * NPAD))[c] = ((const uint4*)(Wh + (size_t)row * 96))[c];
    }

    #pragma unroll 1
    for (int t = 0; t < 8; t++) {
        int row = wid * 8 + t;
        int node = blockRow + row;
        if (node < M) {
            int beg = g_offsets[node];
            int end = g_offsets[node + 1];
            float2 A0 = {0.f, 0.f}, B0 = {0.f, 0.f}, A1 = {0.f, 0.f}, B1 = {0.f, 0.f};
            agg_core(hh_in, layer, beg, end, lane, lo, A0, B0, A1, B1);
            uint32_t* orow = (uint32_t*)(As + row * KPAD);
            __half2 hv;
            hv = __float22half2_rn(A0); orow[lane]      = *(uint32_t*)&hv;
            hv = __float22half2_rn(B0); orow[48 + lane] = *(uint32_t*)&hv;
            if (lo) {
                hv = __float22half2_rn(A1); orow[32 + lane] = *(uint32_t*)&hv;
                hv = __float22half2_rn(B1); orow[80 + lane] = *(uint32_t*)&hv;
            }
        }
    }
    __syncthreads();

    int m0w = (wid & 3) * 16;
    int n0w = (wid >> 2) * 48;
    float acc[6][4];
    #pragma unroll
    for (int nj = 0; nj < 6; nj++)
        #pragma unroll
        for (int q = 0; q < 4; q++) acc[nj][q] = 0.f;

    uint32_t aBase = smem_u32(As), bBase = smem_u32(Bs);
    #pragma unroll
    for (int ks = 0; ks < K / 16; ks++) {
        int k0 = ks * 16;
        uint32_t a[4];
        {
            uint32_t addr = aBase +
                (((m0w + (lane & 7) + (lane & 8)) * KPAD + k0 + ((lane >> 4) << 3)) << 1);
            ldmatrix_x4(a, addr);
        }
        uint32_t b[6][2];
        #pragma unroll
        for (int bj = 0; bj < 3; bj++) {
            uint32_t r[4];
            uint32_t addr = bBase +
                (((k0 + (lane & 15)) * NPAD + n0w + bj * 16 + ((lane >> 4) << 3)) << 1);
            ldmatrix_x4_t(r, addr);
            b[2 * bj][0] = r[0]; b[2 * bj][1] = r[1];
            b[2 * bj + 1][0] = r[2]; b[2 * bj + 1][1] = r[3];
        }
        #pragma unroll
        for (int nj = 0; nj < 6; nj++)
            mma16816(acc[nj], a, b[nj]);
    }

    #pragma unroll
    for (int nj = 0; nj < 6; nj++) {
        int col = n0w + nj * 8 + 2 * (lane & 3);
        int r = blockRow + m0w + (lane >> 2);
        float v0 = fmaxf(acc[nj][0], 0.f);
        float v1 = fmaxf(acc[nj][1], 0.f);
        float v2 = fmaxf(acc[nj][2], 0.f);
        float v3 = fmaxf(acc[nj][3], 0.f);
        if (r < M) {
            __half2 h = __float22half2_rn(make_float2(v0, v1));
            hh_out[(size_t)r * HWORDS + (col >> 1)] = *(uint32_t*)&h;
            if (TAIL) *(float2*)(outTail + (size_t)r * H_DIM + col) = make_float2(v0, v1);
        }
        if (r + 8 < M) {
            __half2 h = __float22half2_rn(make_float2(v2, v3));
            hh_out[(size_t)(r + 8) * HWORDS + (col >> 1)] = *(uint32_t*)&h;
            if (TAIL) *(float2*)(outTail + (size_t)(r + 8) * H_DIM + col) = make_float2(v2, v3);
        }
    }
}

// ---------------- HMMA GEMM (encoder, fp16 out) ----------------
template <int K, bool BIAS>
__global__ void __launch_bounds__(128)
mma_gemm(const __half* __restrict__ Ag, const __half* __restrict__ Wh,
         const float* __restrict__ bias, uint32_t* __restrict__ hh, int M) {
    constexpr int KPAD = (K == 192) ? 200 : 136;
    constexpr int NPAD = 104;
    extern __shared__ __half sm[];
    __half* As = sm;
    __half* Bs = sm + 64 * KPAD;
    int tid = threadIdx.x, lane = tid & 31, wid = tid >> 5;
    int blockRow = blockIdx.x * 64;

    constexpr int ACH = K / 8;
    for (int i = tid; i < 64 * ACH; i += 128) {
        int row = i / ACH, c = i % ACH;
        int gRow = blockRow + row;
        uint4 v = make_uint4(0, 0, 0, 0);
        if (gRow < M) v = ((const uint4*)(Ag + (size_t)gRow * K))[c];
        ((uint4*)(As + row * KPAD))[c] = v;
    }
    for (int i = tid; i < K * 12; i += 128) {
        int row = i / 12, c = i % 12;
        ((uint4*)(Bs + row * NPAD))[c] = ((const uint4*)(Wh + (size_t)row * 96))[c];
    }
    __syncthreads();

    int m0w = (wid & 1) * 32;
    int n0w = (wid >> 1) * 48;
    float acc[2][6][4];
    #pragma unroll
    for (int mi = 0; mi < 2; mi++)
        #pragma unroll
        for (int nj = 0; nj < 6; nj++)
            #pragma unroll
            for (int q = 0; q < 4; q++) acc[mi][nj][q] = 0.f;

    uint32_t aBase = smem_u32(As), bBase = smem_u32(Bs);
    #pragma unroll
    for (int ks = 0; ks < K / 16; ks++) {
        int k0 = ks * 16;
        uint32_t a[2][4];
        #pragma unroll
        for (int mi = 0; mi < 2; mi++) {
            uint32_t addr = aBase +
                (((m0w + mi * 16 + (lane & 7) + (lane & 8)) * KPAD + k0 + ((lane >> 4) << 3)) << 1);
            ldmatrix_x4(a[mi], addr);
        }
        uint32_t b[6][2];
        #pragma unroll
        for (int bj = 0; bj < 3; bj++) {
            uint32_t r[4];
            uint32_t addr = bBase +
                (((k0 + (lane & 15)) * NPAD + n0w + bj * 16 + ((lane >> 4) << 3)) << 1);
            ldmatrix_x4_t(r, addr);
            b[2 * bj][0] = r[0]; b[2 * bj][1] = r[1];
            b[2 * bj + 1][0] = r[2]; b[2 * bj + 1][1] = r[3];
        }
        #pragma unroll
        for (int mi = 0; mi < 2; mi++)
            #pragma unroll
            for (int nj = 0; nj < 6; nj++)
                mma16816(acc[mi][nj], a[mi], b[nj]);
    }

    #pragma unroll
    for (int mi = 0; mi < 2; mi++) {
        #pragma unroll
        for (int nj = 0; nj < 6; nj++) {
            int col = n0w + nj * 8 + 2 * (lane & 3);
            float bx = 0.f, by = 0.f;
            if (BIAS) { float2 bb = *(const float2*)(bias + col); bx = bb.x; by = bb.y; }
            int r = blockRow + m0w + mi * 16 + (lane >> 2);
            float v0 = fmaxf(acc[mi][nj][0] + bx, 0.f);
            float v1 = fmaxf(acc[mi][nj][1] + by, 0.f);
            float v2 = fmaxf(acc[mi][nj][2] + bx, 0.f);
            float v3 = fmaxf(acc[mi][nj][3] + by, 0.f);
            if (r < M) {
                __half2 h = __float22half2_rn(make_float2(v0, v1));
                hh[(size_t)r * HWORDS + (col >> 1)] = *(uint32_t*)&h;
            }
            if (r + 8 < M) {
                __half2 h = __float22half2_rn(make_float2(v2, v3));
                hh[(size_t)(r + 8) * HWORDS + (col >> 1)] = *(uint32_t*)&h;
            }
        }
    }
}

// ---------------- decoder HMMA: out[M x 64] = h(fp16) @ dec_w(fp16) + dec_b, fp32 out ----------------
__global__ void __launch_bounds__(128)
dec_gemm(const uint32_t* __restrict__ hh, const __half* __restrict__ Wh,
         const float* __restrict__ bias, float* __restrict__ out, int M) {
    constexpr int K = 96, KPAD = 104, NPAD = 72;
    extern __shared__ __half sm[];
    __half* As = sm;                 // [64][104]
    __half* Bs = sm + 64 * KPAD;     // [96][72]
    int tid = threadIdx.x, lane = tid & 31, wid = tid >> 5;
    int blockRow = blockIdx.x * 64;

    // A: 64 rows x 12 uint4 (96 halves)
    for (int i = tid; i < 64 * 12; i += 128) {
        int row = i / 12, c = i % 12;
        int gRow = blockRow + row;
        uint4 v = make_uint4(0, 0, 0, 0);
        if (gRow < M) v = ((const uint4*)(hh + (size_t)gRow * HWORDS))[c];
        ((uint4*)(As + row * KPAD))[c] = v;
    }
    // B: 96 rows x 8 uint4 (64 halves)
    for (int i = tid; i < 96 * 8; i += 128) {
        int row = i / 8, c = i % 8;
        ((uint4*)(Bs + row * NPAD))[c] = ((const uint4*)(Wh + (size_t)row * 64))[c];
    }
    __syncthreads();

    int m0w = (wid & 1) * 32;
    int n0w = (wid >> 1) * 32;
    float acc[2][4][4];
    #pragma unroll
    for (int mi = 0; mi < 2; mi++)
        #pragma unroll
        for (int nj = 0; nj < 4; nj++)
            #pragma unroll
            for (int q = 0; q < 4; q++) acc[mi][nj][q] = 0.f;

    uint32_t aBase = smem_u32(As), bBase = smem_u32(Bs);
    #pragma unroll
    for (int ks = 0; ks < K / 16; ks++) {
        int k0 = ks * 16;
        uint32_t a[2][4];
        #pragma unroll
        for (int mi = 0; mi < 2; mi++) {
            uint32_t addr = aBase +
                (((m0w + mi * 16 + (lane & 7) + (lane & 8)) * KPAD + k0 + ((lane >> 4) << 3)) << 1);
            ldmatrix_x4(a[mi], addr);
        }
        uint32_t b[4][2];
        #pragma unroll
        for (int bj = 0; bj < 2; bj++) {
            uint32_t r[4];
            uint32_t addr = bBase +
                (((k0 + (lane & 15)) * NPAD + n0w + bj * 16 + ((lane >> 4) << 3)) << 1);
            ldmatrix_x4_t(r, addr);
            b[2 * bj][0] = r[0]; b[2 * bj][1] = r[1];
            b[2 * bj + 1][0] = r[2]; b[2 * bj + 1][1] = r[3];
        }
        #pragma unroll
        for (int mi = 0; mi < 2; mi++)
            #pragma unroll
            for (int nj = 0; nj < 4; nj++)
                mma16816(acc[mi][nj], a[mi], b[nj]);
    }

    #pragma unroll
    for (int mi = 0; mi < 2; mi++) {
        #pragma unroll
        for (int nj = 0; nj < 4; nj++) {
            int col = n0w + nj * 8 + 2 * (lane & 3);
            float2 bb = *(const float2*)(bias + col);
            int r = blockRow + m0w + mi * 16 + (lane >> 2);
            if (r < M)
                *(float2*)(out + (size_t)r * OUT_DIM + col) =
                    make_float2(acc[mi][nj][0] + bb.x, acc[mi][nj][1] + bb.y);
            if (r + 8 < M)
                *(float2*)(out + (size_t)(r + 8) * OUT_DIM + col) =
                    make_float2(acc[mi][nj][2] + bb.x, acc[mi][nj][3] + bb.y);
        }
    }
}

// ---------------- launch (single stream) ----------------
extern "C" void kernel_launch(void* const* d_in, const int* in_sizes, int n_in,
                              void* d_out, int out_size) {
    const float* x       = (const float*)d_in[0];
    const int*   eidx    = (const int*)d_in[1];
    const float* enc_w   = (const float*)d_in[2];
    const float* enc_b   = (const float*)d_in[3];
    const float* dec_w   = (const float*)d_in[4];
    const float* dec_b   = (const float*)d_in[5];
    const float* conv_W  = (const float*)d_in[6];
    const float* conv_ew = (const float*)d_in[7];
    float* out = (float*)d_out;

    const int* src = eidx;
    const int* dst = eidx + E_EDGES;

    void *p_hh0, *p_hh1, *p_counts, *p_wh, *p_xh;
    cudaGetSymbolAddress(&p_hh0, g_hh0);
    cudaGetSymbolAddress(&p_hh1, g_hh1);
    cudaGetSymbolAddress(&p_counts, g_counts);
    cudaGetSymbolAddress(&p_wh, g_whalf);
    cudaGetSymbolAddress(&p_xh, g_xh);
    uint32_t* hh0 = (uint32_t*)p_hh0;
    uint32_t* hh1 = (uint32_t*)p_hh1;
    const __half* wh = (const __half*)p_wh;
    const __half* xh = (const __half*)p_xh;

    constexpr int SMEM_FUSED = (64 * 200 + 192 * 104) * 2;   // 65536
    constexpr int SMEM_ENC   = (64 * 136 + 128 * 104) * 2;   // 44032
    constexpr int SMEM_DEC   = (64 * 104 + 96 * 72) * 2;     // 27136
    cudaFuncSetAttribute(fused_layer<false>, cudaFuncAttributeMaxDynamicSharedMemorySize, SMEM_FUSED);
    cudaFuncSetAttribute(fused_layer<true>,  cudaFuncAttributeMaxDynamicSharedMemorySize, SMEM_FUSED);
    cudaFuncSetAttribute(mma_gemm<128, true>, cudaFuncAttributeMaxDynamicSharedMemorySize, SMEM_ENC);

    // CSR build + fp16 prep
    cudaMemsetAsync(p_counts, 0, N_NODES * sizeof(int));
    hist_kernel<<<(E_EDGES + 255) / 256, 256>>>(dst);
    block_scan_kernel<<<NB_SCAN, 1024>>>();
    add_base_kernel<<<(N_NODES + 256) / 256, 256>>>();
    scatter_kernel<<<(E_EDGES + 255) / 256, 256>>>(src, dst, conv_ew);
    wprep_kernel<<<(WTOTAL / 2 + 255) / 256, 256>>>(enc_w, conv_W, dec_w);
    xprep_kernel<<<(N_NODES * IN_DIM / 2 + 255) / 256, 256>>>(x);

    int gemmGrid = (N_NODES + 63) / 64;

    // encoder (HMMA): hh0 = relu(x @ enc_w + enc_b)
    mma_gemm<128, true><<<gemmGrid, 128, SMEM_ENC>>>(xh, wh, enc_b, hh0, N_NODES);

    // layers 0..2: fused aggregate+GEMM, double-buffered
    uint32_t* cur = hh0;
    uint32_t* nxt = hh1;
    for (int l = 0; l < NUM_LAYERS - 1; l++) {
        fused_layer<false><<<gemmGrid, 256, SMEM_FUSED>>>(
            cur, l, wh + WOFF_CONV + l * 18432, nxt, nullptr, N_NODES);
        uint32_t* t = cur; cur = nxt; nxt = t;
    }
    // layer 3: fused HMMA, fp32 accumulators also written to out tail
    fused_layer<true><<<gemmGrid, 256, SMEM_FUSED>>>(
        cur, NUM_LAYERS - 1, wh + WOFF_CONV + (NUM_LAYERS - 1) * 18432, nxt,
        out + (size_t)N_NODES * OUT_DIM, N_NODES);
    cur = nxt;

    // decoder (HMMA, fp32 out)
    dec_gemm<<<gemmGrid, 128, SMEM_DEC>>>(cur, wh + WOFF_DEC, dec_b, out, N_NODES);
    (void)in_sizes; (void)n_in; (void)out_size;
}

// round 17
// speedup vs baseline: 1.1970x; 1.0085x over previous
#include <cuda_runtime.h>
#include <cuda_fp16.h>
#include <cstdint>

#define N_NODES 50000
#define E_EDGES 800000
#define IN_DIM  128
#define H_DIM   96
#define OUT_DIM 64
#define NUM_LAYERS 4
#define NB_SCAN ((N_NODES + 1023) / 1024)
#define HWORDS  48   // 96 channels as half2 words

// weight image offsets (halves)
#define WOFF_CONV 12288
#define WOFF_DEC  (12288 + 4 * 18432)
#define WTOTAL    (12288 + 4 * 18432 + 6144)
#define XWORDS    (N_NODES * IN_DIM / 2)

// ---------------- static device scratch ----------------
__device__ uint32_t g_hh0[(size_t)N_NODES * HWORDS];         // h fp16, buffer 0
__device__ uint32_t g_hh1[(size_t)N_NODES * HWORDS];         // h fp16, buffer 1
__device__ uint32_t g_xh[XWORDS];                            // x as half2
__device__ uint32_t g_whalf[WTOTAL / 2];                     // enc_w + conv_W[0..3] + dec_w fp16
__device__ int      g_counts[N_NODES];                       // zero-init; self-restoring
__device__ int      g_offsets[N_NODES + 1];
__device__ int      g_cursor[N_NODES];
__device__ int      g_src_sorted[E_EDGES];
__device__ float2   g_ews[(size_t)E_EDGES * NUM_LAYERS];
__device__ int      g_bsum[NB_SCAN + 1];

// ---------------- helpers ----------------
__device__ __forceinline__ uint32_t smem_u32(const void* p) {
    uint32_t a;
    asm("{ .reg .u64 t; cvta.to.shared.u64 t, %1; cvt.u32.u64 %0, t; }" : "=r"(a) : "l"(p));
    return a;
}
__device__ __forceinline__ void ldmatrix_x4(uint32_t* r, uint32_t addr) {
    asm volatile("ldmatrix.sync.aligned.m8n8.x4.shared.b16 {%0,%1,%2,%3}, [%4];"
                 : "=r"(r[0]), "=r"(r[1]), "=r"(r[2]), "=r"(r[3]) : "r"(addr));
}
__device__ __forceinline__ void ldmatrix_x4_t(uint32_t* r, uint32_t addr) {
    asm volatile("ldmatrix.sync.aligned.m8n8.x4.trans.shared.b16 {%0,%1,%2,%3}, [%4];"
                 : "=r"(r[0]), "=r"(r[1]), "=r"(r[2]), "=r"(r[3]) : "r"(addr));
}
__device__ __forceinline__ void mma16816(float* c, const uint32_t* a, const uint32_t* b) {
    asm volatile("mma.sync.aligned.m16n8k16.row.col.f32.f16.f16.f32 "
                 "{%0,%1,%2,%3},{%4,%5,%6,%7},{%8,%9},{%0,%1,%2,%3};"
                 : "+f"(c[0]), "+f"(c[1]), "+f"(c[2]), "+f"(c[3])
                 : "r"(a[0]), "r"(a[1]), "r"(a[2]), "r"(a[3]), "r"(b[0]), "r"(b[1]));
}

// ---------------- CSR build ----------------
__global__ void hist_kernel(const int* __restrict__ dst) {
    int e = blockIdx.x * blockDim.x + threadIdx.x;
    if (e < E_EDGES) atomicAdd(&g_counts[dst[e]], 1);
}

__global__ void block_scan_kernel() {
    __shared__ int sh[1024];
    int t = threadIdx.x;
    int i = blockIdx.x * 1024 + t;
    int v = (i < N_NODES) ? g_counts[i] : 0;
    sh[t] = v;
    __syncthreads();
    #pragma unroll
    for (int off = 1; off < 1024; off <<= 1) {
        int x = (t >= off) ? sh[t - off] : 0;
        __syncthreads();
        sh[t] += x;
        __syncthreads();
    }
    if (i < N_NODES) g_offsets[i] = sh[t] - v;
    if (t == 1023) g_bsum[blockIdx.x] = sh[1023];
}

__global__ void add_base_kernel() {
    __shared__ int pref[NB_SCAN + 1];
    if (threadIdx.x == 0) {
        int run = 0;
        #pragma unroll
        for (int i = 0; i < NB_SCAN; i++) { pref[i] = run; run += g_bsum[i]; }
        pref[NB_SCAN] = run;
    }
    __syncthreads();
    int i = blockIdx.x * blockDim.x + threadIdx.x;
    if (i < N_NODES) {
        int o = g_offsets[i] + pref[i >> 10];
        g_offsets[i] = o;
        g_cursor[i] = o;
        g_counts[i] = 0;   // restore zero-invariant for next launch (replaces memset)
    }
    if (i == N_NODES) g_offsets[N_NODES] = pref[NB_SCAN];
}

__global__ void scatter_kernel(const int* __restrict__ src,
                               const int* __restrict__ dst,
                               const float* __restrict__ conv_ew) {
    int e = blockIdx.x * blockDim.x + threadIdx.x;
    if (e >= E_EDGES) return;
    int d = dst[e];
    int pos = atomicAdd(&g_cursor[d], 1);
    g_src_sorted[pos] = src[e];
    #pragma unroll
    for (int l = 0; l < NUM_LAYERS; l++) {
        float w0 = conv_ew[(size_t)(l * 2 + 0) * E_EDGES + e];
        float w1 = conv_ew[(size_t)(l * 2 + 1) * E_EDGES + e];
        g_ews[(size_t)pos * NUM_LAYERS + l] = make_float2(w0, w1);
    }
}

// ---------------- fp16 prep (x + all weights, one kernel) ----------------
__global__ void prep_kernel(const float* __restrict__ x,
                            const float* __restrict__ enc_w,
                            const float* __restrict__ conv_W,
                            const float* __restrict__ dec_w) {
    int i = blockIdx.x * blockDim.x + threadIdx.x;
    const int wtot = WTOTAL / 2;
    if (i < XWORDS) {
        float2 v = *(const float2*)(x + i * 2);
        __half2 h = __float22half2_rn(v);
        g_xh[i] = *(uint32_t*)&h;
    } else if (i < XWORDS + wtot) {
        int wi = i - XWORDS;
        int off = wi * 2;
        float2 v;
        if (off < WOFF_CONV)     v = *(const float2*)(enc_w + off);
        else if (off < WOFF_DEC) v = *(const float2*)(conv_W + (off - WOFF_CONV));
        else                     v = *(const float2*)(dec_w + (off - WOFF_DEC));
        __half2 h = __float22half2_rn(v);
        g_whalf[wi] = *(uint32_t*)&h;
    }
}

// ---------------- per-node aggregation core ----------------
// Lane mapping: lane < 24 owns channels 4*lane .. 4*lane+3 (one uint2 = 2 half2 words).
// fa[0..3]/fb[0..3] = head0/head1 channels 4l..4l+3. ONE LDG.64 per edge for h.
__device__ __forceinline__ void agg_core(const uint32_t* __restrict__ hh, int layer,
                                         int beg, int end, int lane, bool act,
                                         float* fa, float* fb) {
    int j = beg;
    int off2 = 2 * (act ? lane : 0);
    for (; j + 7 < end; j += 8) {
        int s[8];
        float2 w[8];
        #pragma unroll
        for (int q = 0; q < 8; q++) {
            s[q] = g_src_sorted[j + q];
            w[q] = g_ews[(size_t)(j + q) * NUM_LAYERS + layer];
        }
        uint2 u[8];
        #pragma unroll
        for (int q = 0; q < 8; q++)
            u[q] = *(const uint2*)(hh + (size_t)s[q] * HWORDS + off2);
        #pragma unroll
        for (int q = 0; q < 8; q++) {
            float2 x0 = __half22float2(*(__half2*)&u[q].x);
            float2 x1 = __half22float2(*(__half2*)&u[q].y);
            fa[0] += w[q].x * x0.x; fa[1] += w[q].x * x0.y;
            fa[2] += w[q].x * x1.x; fa[3] += w[q].x * x1.y;
            fb[0] += w[q].y * x0.x; fb[1] += w[q].y * x0.y;
            fb[2] += w[q].y * x1.x; fb[3] += w[q].y * x1.y;
        }
    }
    for (; j + 3 < end; j += 4) {
        int s[4];
        float2 w[4];
        #pragma unroll
        for (int q = 0; q < 4; q++) {
            s[q] = g_src_sorted[j + q];
            w[q] = g_ews[(size_t)(j + q) * NUM_LAYERS + layer];
        }
        uint2 u[4];
        #pragma unroll
        for (int q = 0; q < 4; q++)
            u[q] = *(const uint2*)(hh + (size_t)s[q] * HWORDS + off2);
        #pragma unroll
        for (int q = 0; q < 4; q++) {
            float2 x0 = __half22float2(*(__half2*)&u[q].x);
            float2 x1 = __half22float2(*(__half2*)&u[q].y);
            fa[0] += w[q].x * x0.x; fa[1] += w[q].x * x0.y;
            fa[2] += w[q].x * x1.x; fa[3] += w[q].x * x1.y;
            fb[0] += w[q].y * x0.x; fb[1] += w[q].y * x0.y;
            fb[2] += w[q].y * x1.x; fb[3] += w[q].y * x1.y;
        }
    }
    for (; j < end; j++) {
        int s = g_src_sorted[j];
        float2 w = g_ews[(size_t)j * NUM_LAYERS + layer];
        uint2 u = *(const uint2*)(hh + (size_t)s * HWORDS + off2);
        float2 x0 = __half22float2(*(__half2*)&u.x);
        float2 x1 = __half22float2(*(__half2*)&u.y);
        fa[0] += w.x * x0.x; fa[1] += w.x * x0.y;
        fa[2] += w.x * x1.x; fa[3] += w.x * x1.y;
        fb[0] += w.y * x0.x; fb[1] += w.y * x0.y;
        fb[2] += w.y * x1.x; fb[3] += w.y * x1.y;
    }
}

// ---------------- fused conv layer: aggregate (into SMEM) + HMMA GEMM ----------------
// TAIL: also write fp32 accumulator results (relu'd, pre-fp16-rounding) to outTail.
template <bool TAIL>
__global__ void __launch_bounds__(256)
fused_layer(const uint32_t* __restrict__ hh_in, int layer,
            const __half* __restrict__ Wh, uint32_t* __restrict__ hh_out,
            float* __restrict__ outTail, int M) {
    constexpr int K = 192, KPAD = 200, NPAD = 104;
    extern __shared__ __half sm[];
    __half* As = sm;                 // [64][200]
    __half* Bs = sm + 64 * KPAD;     // [192][104]
    int tid = threadIdx.x, lane = tid & 31, wid = tid >> 5;
    int blockRow = blockIdx.x * 64;
    bool act = lane < 24;

    for (int i = tid; i < K * 12; i += 256) {
        int row = i / 12, c = i % 12;
        ((uint4*)(Bs + row * NPAD))[c] = ((const uint4*)(Wh + (size_t)row * 96))[c];
    }

    #pragma unroll 1
    for (int t = 0; t < 8; t++) {
        int row = wid * 8 + t;
        int node = blockRow + row;
        if (node < M) {
            int beg = g_offsets[node];
            int end = g_offsets[node + 1];
            float fa[4] = {0.f, 0.f, 0.f, 0.f};
            float fb[4] = {0.f, 0.f, 0.f, 0.f};
            agg_core(hh_in, layer, beg, end, lane, act, fa, fb);
            if (act) {
                uint32_t* orow = (uint32_t*)(As + row * KPAD);
                __half2 hv;
                hv = __float22half2_rn(make_float2(fa[0], fa[1])); orow[2 * lane]      = *(uint32_t*)&hv;
                hv = __float22half2_rn(make_float2(fa[2], fa[3])); orow[2 * lane + 1]  = *(uint32_t*)&hv;
                hv = __float22half2_rn(make_float2(fb[0], fb[1])); orow[48 + 2 * lane] = *(uint32_t*)&hv;
                hv = __float22half2_rn(make_float2(fb[2], fb[3])); orow[49 + 2 * lane] = *(uint32_t*)&hv;
            }
        }
    }
    __syncthreads();

    int m0w = (wid & 3) * 16;
    int n0w = (wid >> 2) * 48;
    float acc[6][4];
    #pragma unroll
    for (int nj = 0; nj < 6; nj++)
        #pragma unroll
        for (int q = 0; q < 4; q++) acc[nj][q] = 0.f;

    uint32_t aBase = smem_u32(As), bBase = smem_u32(Bs);
    #pragma unroll
    for (int ks = 0; ks < K / 16; ks++) {
        int k0 = ks * 16;
        uint32_t a[4];
        {
            uint32_t addr = aBase +
                (((m0w + (lane & 7) + (lane & 8)) * KPAD + k0 + ((lane >> 4) << 3)) << 1);
            ldmatrix_x4(a, addr);
        }
        uint32_t b[6][2];
        #pragma unroll
        for (int bj = 0; bj < 3; bj++) {
            uint32_t r[4];
            uint32_t addr = bBase +
                (((k0 + (lane & 15)) * NPAD + n0w + bj * 16 + ((lane >> 4) << 3)) << 1);
            ldmatrix_x4_t(r, addr);
            b[2 * bj][0] = r[0]; b[2 * bj][1] = r[1];
            b[2 * bj + 1][0] = r[2]; b[2 * bj + 1][1] = r[3];
        }
        #pragma unroll
        for (int nj = 0; nj < 6; nj++)
            mma16816(acc[nj], a, b[nj]);
    }

    #pragma unroll
    for (int nj = 0; nj < 6; nj++) {
        int col = n0w + nj * 8 + 2 * (lane & 3);
        int r = blockRow + m0w + (lane >> 2);
        float v0 = fmaxf(acc[nj][0], 0.f);
        float v1 = fmaxf(acc[nj][1], 0.f);
        float v2 = fmaxf(acc[nj][2], 0.f);
        float v3 = fmaxf(acc[nj][3], 0.f);
        if (r < M) {
            __half2 h = __float22half2_rn(make_float2(v0, v1));
            hh_out[(size_t)r * HWORDS + (col >> 1)] = *(uint32_t*)&h;
            if (TAIL) *(float2*)(outTail + (size_t)r * H_DIM + col) = make_float2(v0, v1);
        }
        if (r + 8 < M) {
            __half2 h = __float22half2_rn(make_float2(v2, v3));
            hh_out[(size_t)(r + 8) * HWORDS + (col >> 1)] = *(uint32_t*)&h;
            if (TAIL) *(float2*)(outTail + (size_t)(r + 8) * H_DIM + col) = make_float2(v2, v3);
        }
    }
}

// ---------------- HMMA GEMM (encoder, fp16 out) ----------------
template <int K, bool BIAS>
__global__ void __launch_bounds__(128)
mma_gemm(const __half* __restrict__ Ag, const __half* __restrict__ Wh,
         const float* __restrict__ bias, uint32_t* __restrict__ hh, int M) {
    constexpr int KPAD = (K == 192) ? 200 : 136;
    constexpr int NPAD = 104;
    extern __shared__ __half sm[];
    __half* As = sm;
    __half* Bs = sm + 64 * KPAD;
    int tid = threadIdx.x, lane = tid & 31, wid = tid >> 5;
    int blockRow = blockIdx.x * 64;

    constexpr int ACH = K / 8;
    for (int i = tid; i < 64 * ACH; i += 128) {
        int row = i / ACH, c = i % ACH;
        int gRow = blockRow + row;
        uint4 v = make_uint4(0, 0, 0, 0);
        if (gRow < M) v = ((const uint4*)(Ag + (size_t)gRow * K))[c];
        ((uint4*)(As + row * KPAD))[c] = v;
    }
    for (int i = tid; i < K * 12; i += 128) {
        int row = i / 12, c = i % 12;
        ((uint4*)(Bs + row * NPAD))[c] = ((const uint4*)(Wh + (size_t)row * 96))[c];
    }
    __syncthreads();

    int m0w = (wid & 1) * 32;
    int n0w = (wid >> 1) * 48;
    float acc[2][6][4];
    #pragma unroll
    for (int mi = 0; mi < 2; mi++)
        #pragma unroll
        for (int nj = 0; nj < 6; nj++)
            #pragma unroll
            for (int q = 0; q < 4; q++) acc[mi][nj][q] = 0.f;

    uint32_t aBase = smem_u32(As), bBase = smem_u32(Bs);
    #pragma unroll
    for (int ks = 0; ks < K / 16; ks++) {
        int k0 = ks * 16;
        uint32_t a[2][4];
        #pragma unroll
        for (int mi = 0; mi < 2; mi++) {
            uint32_t addr = aBase +
                (((m0w + mi * 16 + (lane & 7) + (lane & 8)) * KPAD + k0 + ((lane >> 4) << 3)) << 1);
            ldmatrix_x4(a[mi], addr);
        }
        uint32_t b[6][2];
        #pragma unroll
        for (int bj = 0; bj < 3; bj++) {
            uint32_t r[4];
            uint32_t addr = bBase +
                (((k0 + (lane & 15)) * NPAD + n0w + bj * 16 + ((lane >> 4) << 3)) << 1);
            ldmatrix_x4_t(r, addr);
            b[2 * bj][0] = r[0]; b[2 * bj][1] = r[1];
            b[2 * bj + 1][0] = r[2]; b[2 * bj + 1][1] = r[3];
        }
        #pragma unroll
        for (int mi = 0; mi < 2; mi++)
            #pragma unroll
            for (int nj = 0; nj < 6; nj++)
                mma16816(acc[mi][nj], a[mi], b[nj]);
    }

    #pragma unroll
    for (int mi = 0; mi < 2; mi++) {
        #pragma unroll
        for (int nj = 0; nj < 6; nj++) {
            int col = n0w + nj * 8 + 2 * (lane & 3);
            float bx = 0.f, by = 0.f;
            if (BIAS) { float2 bb = *(const float2*)(bias + col); bx = bb.x; by = bb.y; }
            int r = blockRow + m0w + mi * 16 + (lane >> 2);
            float v0 = fmaxf(acc[mi][nj][0] + bx, 0.f);
            float v1 = fmaxf(acc[mi][nj][1] + by, 0.f);
            float v2 = fmaxf(acc[mi][nj][2] + bx, 0.f);
            float v3 = fmaxf(acc[mi][nj][3] + by, 0.f);
            if (r < M) {
                __half2 h = __float22half2_rn(make_float2(v0, v1));
                hh[(size_t)r * HWORDS + (col >> 1)] = *(uint32_t*)&h;
            }
            if (r + 8 < M) {
                __half2 h = __float22half2_rn(make_float2(v2, v3));
                hh[(size_t)(r + 8) * HWORDS + (col >> 1)] = *(uint32_t*)&h;
            }
        }
    }
}

// ---------------- decoder HMMA: out[M x 64] = h(fp16) @ dec_w(fp16) + dec_b, fp32 out ----------------
__global__ void __launch_bounds__(128)
dec_gemm(const uint32_t* __restrict__ hh, const __half* __restrict__ Wh,
         const float* __restrict__ bias, float* __restrict__ out, int M) {
    constexpr int K = 96, KPAD = 104, NPAD = 72;
    extern __shared__ __half sm[];
    __half* As = sm;                 // [64][104]
    __half* Bs = sm + 64 * KPAD;     // [96][72]
    int tid = threadIdx.x, lane = tid & 31, wid = tid >> 5;
    int blockRow = blockIdx.x * 64;

    for (int i = tid; i < 64 * 12; i += 128) {
        int row = i / 12, c = i % 12;
        int gRow = blockRow + row;
        uint4 v = make_uint4(0, 0, 0, 0);
        if (gRow < M) v = ((const uint4*)(hh + (size_t)gRow * HWORDS))[c];
        ((uint4*)(As + row * KPAD))[c] = v;
    }
    for (int i = tid; i < 96 * 8; i += 128) {
        int row = i / 8, c = i % 8;
        ((uint4*)(Bs + row * NPAD))[c] = ((const uint4*)(Wh + (size_t)row * 64))[c];
    }
    __syncthreads();

    int m0w = (wid & 1) * 32;
    int n0w = (wid >> 1) * 32;
    float acc[2][4][4];
    #pragma unroll
    for (int mi = 0; mi < 2; mi++)
        #pragma unroll
        for (int nj = 0; nj < 4; nj++)
            #pragma unroll
            for (int q = 0; q < 4; q++) acc[mi][nj][q] = 0.f;

    uint32_t aBase = smem_u32(As), bBase = smem_u32(Bs);
    #pragma unroll
    for (int ks = 0; ks < K / 16; ks++) {
        int k0 = ks * 16;
        uint32_t a[2][4];
        #pragma unroll
        for (int mi = 0; mi < 2; mi++) {
            uint32_t addr = aBase +
                (((m0w + mi * 16 + (lane & 7) + (lane & 8)) * KPAD + k0 + ((lane >> 4) << 3)) << 1);
            ldmatrix_x4(a[mi], addr);
        }
        uint32_t b[4][2];
        #pragma unroll
        for (int bj = 0; bj < 2; bj++) {
            uint32_t r[4];
            uint32_t addr = bBase +
                (((k0 + (lane & 15)) * NPAD + n0w + bj * 16 + ((lane >> 4) << 3)) << 1);
            ldmatrix_x4_t(r, addr);
            b[2 * bj][0] = r[0]; b[2 * bj][1] = r[1];
            b[2 * bj + 1][0] = r[2]; b[2 * bj + 1][1] = r[3];
        }
        #pragma unroll
        for (int mi = 0; mi < 2; mi++)
            #pragma unroll
            for (int nj = 0; nj < 4; nj++)
                mma16816(acc[mi][nj], a[mi], b[nj]);
    }

    #pragma unroll
    for (int mi = 0; mi < 2; mi++) {
        #pragma unroll
        for (int nj = 0; nj < 4; nj++) {
            int col = n0w + nj * 8 + 2 * (lane & 3);
            float2 bb = *(const float2*)(bias + col);
            int r = blockRow + m0w + mi * 16 + (lane >> 2);
            if (r < M)
                *(float2*)(out + (size_t)r * OUT_DIM + col) =
                    make_float2(acc[mi][nj][0] + bb.x, acc[mi][nj][1] + bb.y);
            if (r + 8 < M)
                *(float2*)(out + (size_t)(r + 8) * OUT_DIM + col) =
                    make_float2(acc[mi][nj][2] + bb.x, acc[mi][nj][3] + bb.y);
        }
    }
}

// ---------------- launch (single stream) ----------------
extern "C" void kernel_launch(void* const* d_in, const int* in_sizes, int n_in,
                              void* d_out, int out_size) {
    const float* x       = (const float*)d_in[0];
    const int*   eidx    = (const int*)d_in[1];
    const float* enc_w   = (const float*)d_in[2];
    const float* enc_b   = (const float*)d_in[3];
    const float* dec_w   = (const float*)d_in[4];
    const float* dec_b   = (const float*)d_in[5];
    const float* conv_W  = (const float*)d_in[6];
    const float* conv_ew = (const float*)d_in[7];
    float* out = (float*)d_out;

    const int* src = eidx;
    const int* dst = eidx + E_EDGES;

    void *p_hh0, *p_hh1, *p_wh, *p_xh;
    cudaGetSymbolAddress(&p_hh0, g_hh0);
    cudaGetSymbolAddress(&p_hh1, g_hh1);
    cudaGetSymbolAddress(&p_wh, g_whalf);
    cudaGetSymbolAddress(&p_xh, g_xh);
    uint32_t* hh0 = (uint32_t*)p_hh0;
    uint32_t* hh1 = (uint32_t*)p_hh1;
    const __half* wh = (const __half*)p_wh;
    const __half* xh = (const __half*)p_xh;

    constexpr int SMEM_FUSED = (64 * 200 + 192 * 104) * 2;   // 65536
    constexpr int SMEM_ENC   = (64 * 136 + 128 * 104) * 2;   // 44032
    constexpr int SMEM_DEC   = (64 * 104 + 96 * 72) * 2;     // 27136
    cudaFuncSetAttribute(fused_layer<false>, cudaFuncAttributeMaxDynamicSharedMemorySize, SMEM_FUSED);
    cudaFuncSetAttribute(fused_layer<true>,  cudaFuncAttributeMaxDynamicSharedMemorySize, SMEM_FUSED);
    cudaFuncSetAttribute(mma_gemm<128, true>, cudaFuncAttributeMaxDynamicSharedMemorySize, SMEM_ENC);

    // CSR build + fp16 prep (counts zero-invariant maintained by add_base)
    hist_kernel<<<(E_EDGES + 255) / 256, 256>>>(dst);
    block_scan_kernel<<<NB_SCAN, 1024>>>();
    add_base_kernel<<<(N_NODES + 256) / 256, 256>>>();
    scatter_kernel<<<(E_EDGES + 255) / 256, 256>>>(src, dst, conv_ew);
    prep_kernel<<<(XWORDS + WTOTAL / 2 + 255) / 256, 256>>>(x, enc_w, conv_W, dec_w);

    int gemmGrid = (N_NODES + 63) / 64;

    // encoder (HMMA): hh0 = relu(x @ enc_w + enc_b)
    mma_gemm<128, true><<<gemmGrid, 128, SMEM_ENC>>>(xh, wh, enc_b, hh0, N_NODES);

    // layers 0..2: fused aggregate+GEMM, double-buffered
    uint32_t* cur = hh0;
    uint32_t* nxt = hh1;
    for (int l = 0; l < NUM_LAYERS - 1; l++) {
        fused_layer<false><<<gemmGrid, 256, SMEM_FUSED>>>(
            cur, l, wh + WOFF_CONV + l * 18432, nxt, nullptr, N_NODES);
        uint32_t* t = cur; cur = nxt; nxt = t;
    }
    // layer 3: fused HMMA, fp32 accumulators also written to out tail
    fused_layer<true><<<gemmGrid, 256, SMEM_FUSED>>>(
        cur, NUM_LAYERS - 1, wh + WOFF_CONV + (NUM_LAYERS - 1) * 18432, nxt,
        out + (size_t)N_NODES * OUT_DIM, N_NODES);
    cur = nxt;

    // decoder (HMMA, fp32 out)
    dec_gemm<<<gemmGrid, 128, SMEM_DEC>>>(cur, wh + WOFF_DEC, dec_b, out, N_NODES);
    (void)in_sizes; (void)n_in; (void)out_size;
}